// round 4
// baseline (speedup 1.0000x reference)
#include <cuda_runtime.h>
#include <math.h>
#include <stdint.h>

#define BB   2
#define SS   2048
#define DD   512
#define HH   8
#define DKK  64
#define BHH  (BB*HH)

// ---------------- scratch (device globals; no allocation allowed) ----------
__device__ float g_qh[BHH*SS*DKK];          // [bh][s][dk]  tf32-rounded bits
__device__ float g_kh[BHH*SS*DKK];          // tf32-rounded bits
__device__ float g_vt[BHH*DKK*SS];          // V^T [bh][dk][s], tf32-rounded bits
__device__ float g_at[BB*SS*DD];            // attention out [b][s][h*64+dk]
__device__ float g_cos[SS*DKK];
__device__ float g_sin[SS*DKK];
__device__ float g_sc[67108864];            // raw scores [bh][i][j] 256 MiB

// ---------------- helpers ----------------------------------------------------
__device__ __forceinline__ uint32_t f2tf(float f)
{
    uint32_t u;
    asm("cvt.rna.tf32.f32 %0, %1;" : "=r"(u) : "f"(f));
    return u;
}

__device__ __forceinline__ void mma8(float* c, const uint32_t* a, const uint32_t* b)
{
    asm volatile(
        "mma.sync.aligned.m16n8k8.row.col.f32.tf32.tf32.f32 "
        "{%0,%1,%2,%3}, {%4,%5,%6,%7}, {%8,%9}, {%0,%1,%2,%3};\n"
        : "+f"(c[0]), "+f"(c[1]), "+f"(c[2]), "+f"(c[3])
        : "r"(a[0]), "r"(a[1]), "r"(a[2]), "r"(a[3]), "r"(b[0]), "r"(b[1]));
}

// ---------------- RoPE table ------------------------------------------------
__global__ void rope_tab_kernel()
{
    int idx = blockIdx.x * blockDim.x + threadIdx.x;
    if (idx >= SS * 32) return;
    int s = idx >> 5;
    int m = idx & 31;
    float f = (float)s * powf(10000.f, -(float)(2 * m) / 64.f);
    float sn, cs;
    sincosf(f, &sn, &cs);
    g_cos[s*64 + 2*m]     = cs;
    g_cos[s*64 + 2*m + 1] = cs;
    g_sin[s*64 + 2*m]     = sn;
    g_sin[s*64 + 2*m + 1] = sn;
}

// ---------------- fused QKV projection + RoPE (tf32 mma, reg-prefetch) -------
__global__ __launch_bounds__(256) void proj_kernel(
    const float* __restrict__ qx, const float* __restrict__ kx, const float* __restrict__ vx,
    const float* __restrict__ Wq, const float* __restrict__ bq,
    const float* __restrict__ Wk, const float* __restrict__ bk,
    const float* __restrict__ Wv, const float* __restrict__ bv)
{
    __shared__ uint32_t As[128][36];
    __shared__ uint32_t Bs[128][36];

    int which = blockIdx.z;
    const float* X    = (which == 0) ? qx : (which == 1) ? kx : vx;
    const float* W    = (which == 0) ? Wq : (which == 1) ? Wk : Wv;
    const float* bias = (which == 0) ? bq : (which == 1) ? bk : bv;

    int tid  = threadIdx.x;
    int wid  = tid >> 5, lane = tid & 31;
    int g    = lane >> 2, t = lane & 3;
    int wm   = wid >> 2, wn = wid & 3;
    int n0   = blockIdx.x * 128;
    int m0   = blockIdx.y * 128;

    float c[4][4][4];
    #pragma unroll
    for (int mf = 0; mf < 4; mf++)
        #pragma unroll
        for (int nf = 0; nf < 4; nf++)
            #pragma unroll
            for (int u = 0; u < 4; u++) c[mf][nf][u] = 0.f;

    int lr = tid >> 1;
    int lc = (tid & 1) * 16;

    float4 xa[4], wb[4];
    #pragma unroll
    for (int u = 0; u < 4; u++) {
        xa[u] = *(const float4*)(X + (size_t)(m0 + lr) * 512 + lc + u*4);
        wb[u] = *(const float4*)(W + (size_t)(n0 + lr) * 512 + lc + u*4);
    }
    #pragma unroll
    for (int u = 0; u < 4; u++) {
        As[lr][lc+u*4+0] = f2tf(xa[u].x); As[lr][lc+u*4+1] = f2tf(xa[u].y);
        As[lr][lc+u*4+2] = f2tf(xa[u].z); As[lr][lc+u*4+3] = f2tf(xa[u].w);
        Bs[lr][lc+u*4+0] = f2tf(wb[u].x); Bs[lr][lc+u*4+1] = f2tf(wb[u].y);
        Bs[lr][lc+u*4+2] = f2tf(wb[u].z); Bs[lr][lc+u*4+3] = f2tf(wb[u].w);
    }
    __syncthreads();

    for (int k0 = 0; k0 < 512; k0 += 32) {
        int kn = k0 + 32;
        if (kn < 512) {
            #pragma unroll
            for (int u = 0; u < 4; u++) {
                xa[u] = *(const float4*)(X + (size_t)(m0 + lr) * 512 + kn + lc + u*4);
                wb[u] = *(const float4*)(W + (size_t)(n0 + lr) * 512 + kn + lc + u*4);
            }
        }
        #pragma unroll
        for (int k8 = 0; k8 < 32; k8 += 8) {
            uint32_t a[4][4], b[4][2];
            #pragma unroll
            for (int mf = 0; mf < 4; mf++) {
                int r = wm*64 + mf*16 + g;
                a[mf][0] = As[r][k8+t];     a[mf][1] = As[r+8][k8+t];
                a[mf][2] = As[r][k8+t+4];   a[mf][3] = As[r+8][k8+t+4];
            }
            #pragma unroll
            for (int nf = 0; nf < 4; nf++) {
                int rn = wn*32 + nf*8 + g;
                b[nf][0] = Bs[rn][k8+t];    b[nf][1] = Bs[rn][k8+t+4];
            }
            #pragma unroll
            for (int mf = 0; mf < 4; mf++)
                #pragma unroll
                for (int nf = 0; nf < 4; nf++)
                    mma8(c[mf][nf], a[mf], b[nf]);
        }
        __syncthreads();
        if (kn < 512) {
            #pragma unroll
            for (int u = 0; u < 4; u++) {
                As[lr][lc+u*4+0] = f2tf(xa[u].x); As[lr][lc+u*4+1] = f2tf(xa[u].y);
                As[lr][lc+u*4+2] = f2tf(xa[u].z); As[lr][lc+u*4+3] = f2tf(xa[u].w);
                Bs[lr][lc+u*4+0] = f2tf(wb[u].x); Bs[lr][lc+u*4+1] = f2tf(wb[u].y);
                Bs[lr][lc+u*4+2] = f2tf(wb[u].z); Bs[lr][lc+u*4+3] = f2tf(wb[u].w);
            }
            __syncthreads();
        }
    }

    // ---- epilogue: bias (+ RoPE for q/k); store tf32-rounded bits ----
    #pragma unroll
    for (int nf = 0; nf < 4; nf++) {
        int col = n0 + wn*32 + nf*8 + t*2;
        int hh  = col >> 6, dk = col & 63;
        float bce = bias[col], bco = bias[col+1];
        #pragma unroll
        for (int mf = 0; mf < 4; mf++) {
            #pragma unroll
            for (int half = 0; half < 2; half++) {
                int row  = m0 + wm*64 + mf*16 + g + half*8;
                int srow = row & (SS-1);
                int bidx = row >> 11;
                float e = c[mf][nf][half*2+0] + bce;
                float o = c[mf][nf][half*2+1] + bco;
                if (which < 2) {
                    float cs = g_cos[srow*64 + dk];
                    float sn = g_sin[srow*64 + dk];
                    float ne = __uint_as_float(f2tf(e*cs - o*sn));
                    float no = __uint_as_float(f2tf(o*cs + e*sn));
                    float* Y = (which == 0) ? g_qh : g_kh;
                    *(float2*)(Y + (((size_t)(bidx*HH + hh))*SS + srow)*DKK + dk)
                        = make_float2(ne, no);
                } else {
                    size_t vb = (size_t)(bidx*HH + hh) * DKK;
                    g_vt[(vb + dk    )*SS + srow] = __uint_as_float(f2tf(e));
                    g_vt[(vb + dk + 1)*SS + srow] = __uint_as_float(f2tf(o));
                }
            }
        }
    }
}

// ---------------- output projection (tf32 mma, reg-prefetch) -----------------
__global__ __launch_bounds__(256) void out_proj_kernel(
    const float* __restrict__ W, const float* __restrict__ bias, float* __restrict__ out)
{
    __shared__ uint32_t As[128][36];
    __shared__ uint32_t Bs[128][36];

    int tid  = threadIdx.x;
    int wid  = tid >> 5, lane = tid & 31;
    int g    = lane >> 2, t = lane & 3;
    int wm   = wid >> 2, wn = wid & 3;
    int n0   = blockIdx.x * 128;
    int m0   = blockIdx.y * 128;

    float c[4][4][4];
    #pragma unroll
    for (int mf = 0; mf < 4; mf++)
        #pragma unroll
        for (int nf = 0; nf < 4; nf++)
            #pragma unroll
            for (int u = 0; u < 4; u++) c[mf][nf][u] = 0.f;

    int lr = tid >> 1;
    int lc = (tid & 1) * 16;

    float4 xa[4], wb[4];
    #pragma unroll
    for (int u = 0; u < 4; u++) {
        xa[u] = *(const float4*)(g_at + (size_t)(m0 + lr) * 512 + lc + u*4);
        wb[u] = *(const float4*)(W    + (size_t)(n0 + lr) * 512 + lc + u*4);
    }
    #pragma unroll
    for (int u = 0; u < 4; u++) {
        As[lr][lc+u*4+0] = f2tf(xa[u].x); As[lr][lc+u*4+1] = f2tf(xa[u].y);
        As[lr][lc+u*4+2] = f2tf(xa[u].z); As[lr][lc+u*4+3] = f2tf(xa[u].w);
        Bs[lr][lc+u*4+0] = f2tf(wb[u].x); Bs[lr][lc+u*4+1] = f2tf(wb[u].y);
        Bs[lr][lc+u*4+2] = f2tf(wb[u].z); Bs[lr][lc+u*4+3] = f2tf(wb[u].w);
    }
    __syncthreads();

    for (int k0 = 0; k0 < 512; k0 += 32) {
        int kn = k0 + 32;
        if (kn < 512) {
            #pragma unroll
            for (int u = 0; u < 4; u++) {
                xa[u] = *(const float4*)(g_at + (size_t)(m0 + lr) * 512 + kn + lc + u*4);
                wb[u] = *(const float4*)(W    + (size_t)(n0 + lr) * 512 + kn + lc + u*4);
            }
        }
        #pragma unroll
        for (int k8 = 0; k8 < 32; k8 += 8) {
            uint32_t a[4][4], b[4][2];
            #pragma unroll
            for (int mf = 0; mf < 4; mf++) {
                int r = wm*64 + mf*16 + g;
                a[mf][0] = As[r][k8+t];     a[mf][1] = As[r+8][k8+t];
                a[mf][2] = As[r][k8+t+4];   a[mf][3] = As[r+8][k8+t+4];
            }
            #pragma unroll
            for (int nf = 0; nf < 4; nf++) {
                int rn = wn*32 + nf*8 + g;
                b[nf][0] = Bs[rn][k8+t];    b[nf][1] = Bs[rn][k8+t+4];
            }
            #pragma unroll
            for (int mf = 0; mf < 4; mf++)
                #pragma unroll
                for (int nf = 0; nf < 4; nf++)
                    mma8(c[mf][nf], a[mf], b[nf]);
        }
        __syncthreads();
        if (kn < 512) {
            #pragma unroll
            for (int u = 0; u < 4; u++) {
                As[lr][lc+u*4+0] = f2tf(xa[u].x); As[lr][lc+u*4+1] = f2tf(xa[u].y);
                As[lr][lc+u*4+2] = f2tf(xa[u].z); As[lr][lc+u*4+3] = f2tf(xa[u].w);
                Bs[lr][lc+u*4+0] = f2tf(wb[u].x); Bs[lr][lc+u*4+1] = f2tf(wb[u].y);
                Bs[lr][lc+u*4+2] = f2tf(wb[u].z); Bs[lr][lc+u*4+3] = f2tf(wb[u].w);
            }
            __syncthreads();
        }
    }

    #pragma unroll
    for (int nf = 0; nf < 4; nf++) {
        int col = n0 + wn*32 + nf*8 + t*2;
        float bce = bias[col], bco = bias[col+1];
        #pragma unroll
        for (int mf = 0; mf < 4; mf++) {
            #pragma unroll
            for (int half = 0; half < 2; half++) {
                int row = m0 + wm*64 + mf*16 + g + half*8;
                *(float2*)(out + (size_t)row*512 + col)
                    = make_float2(c[mf][nf][half*2+0] + bce, c[mf][nf][half*2+1] + bco);
            }
        }
    }
}

// ---------------- causal score GEMM S = (Q K^T)/8 (raw tf32 bits) ------------
__global__ __launch_bounds__(256) void score_kernel()
{
    int qt = blockIdx.x, kt = blockIdx.y, bh = blockIdx.z;
    if (kt > qt) return;

    __shared__ uint32_t Qs[128][36];
    __shared__ uint32_t Ks[128][36];

    const uint32_t* qb = (const uint32_t*)g_qh + (size_t)bh * SS * DKK;
    const uint32_t* kb = (const uint32_t*)g_kh + (size_t)bh * SS * DKK;

    int tid  = threadIdx.x;
    int wid  = tid >> 5, lane = tid & 31;
    int g    = lane >> 2, t = lane & 3;
    int wm   = wid >> 2, wn = wid & 3;
    int i0   = qt * 128, j0 = kt * 128;

    float c[4][4][4];
    #pragma unroll
    for (int mf = 0; mf < 4; mf++)
        #pragma unroll
        for (int nf = 0; nf < 4; nf++)
            #pragma unroll
            for (int u = 0; u < 4; u++) c[mf][nf][u] = 0.f;

    int lr = tid >> 1;
    int lc = (tid & 1) * 16;

    uint4 qv[4], kv[4];
    #pragma unroll
    for (int u = 0; u < 4; u++) {
        qv[u] = *(const uint4*)(qb + (size_t)(i0 + lr) * 64 + lc + u*4);
        kv[u] = *(const uint4*)(kb + (size_t)(j0 + lr) * 64 + lc + u*4);
    }
    #pragma unroll
    for (int u = 0; u < 4; u++) {
        *(uint4*)&Qs[lr][lc+u*4] = qv[u];
        *(uint4*)&Ks[lr][lc+u*4] = kv[u];
    }
    __syncthreads();

    #pragma unroll
    for (int k0 = 0; k0 < 64; k0 += 32) {
        int kn = k0 + 32;
        if (kn < 64) {
            #pragma unroll
            for (int u = 0; u < 4; u++) {
                qv[u] = *(const uint4*)(qb + (size_t)(i0 + lr) * 64 + kn + lc + u*4);
                kv[u] = *(const uint4*)(kb + (size_t)(j0 + lr) * 64 + kn + lc + u*4);
            }
        }
        #pragma unroll
        for (int k8 = 0; k8 < 32; k8 += 8) {
            uint32_t a[4][4], b[4][2];
            #pragma unroll
            for (int mf = 0; mf < 4; mf++) {
                int r = wm*64 + mf*16 + g;
                a[mf][0] = Qs[r][k8+t];     a[mf][1] = Qs[r+8][k8+t];
                a[mf][2] = Qs[r][k8+t+4];   a[mf][3] = Qs[r+8][k8+t+4];
            }
            #pragma unroll
            for (int nf = 0; nf < 4; nf++) {
                int rn = wn*32 + nf*8 + g;
                b[nf][0] = Ks[rn][k8+t];    b[nf][1] = Ks[rn][k8+t+4];
            }
            #pragma unroll
            for (int mf = 0; mf < 4; mf++)
                #pragma unroll
                for (int nf = 0; nf < 4; nf++)
                    mma8(c[mf][nf], a[mf], b[nf]);
        }
        __syncthreads();
        if (kn < 64) {
            #pragma unroll
            for (int u = 0; u < 4; u++) {
                *(uint4*)&Qs[lr][lc+u*4] = qv[u];
                *(uint4*)&Ks[lr][lc+u*4] = kv[u];
            }
            __syncthreads();
        }
    }

    float* C = g_sc + (size_t)bh * SS * SS;
    #pragma unroll
    for (int nf = 0; nf < 4; nf++) {
        int col = j0 + wn*32 + nf*8 + t*2;
        #pragma unroll
        for (int mf = 0; mf < 4; mf++) {
            #pragma unroll
            for (int half = 0; half < 2; half++) {
                int row = i0 + wm*64 + mf*16 + g + half*8;
                *(float2*)(C + (size_t)row*SS + col)
                    = make_float2(c[mf][nf][half*2+0] * 0.125f,
                                  c[mf][nf][half*2+1] * 0.125f);
            }
        }
    }
}

// ---------------- fused row-softmax-decay-softmax + PV GEMM -------------------
// One CTA per (qt, bh). Pass 1: per-row exp-prefix table at 16-col granularity
// (no max subtraction needed: |scores| << 80, exp stays finite in fp32).
// Pass 2: rebuild unnormalized P tile-by-tile in smem, tf32 mma against V^T,
// track l2 = sum(e2) per row in registers, scale output by 1/l2 in epilogue.
//
// dynamic smem layout (floats):
//   pre16 [128][129]   exclusive prefix of exp(s) at 16-col chunks
//   l1s   [128]        full-row sum of exp(s)
//   ggs   [128]        -softplus(gamma) per row
//   sl2   [256]        per (row, half-thread) e2 sums
//   Ps    [128*36]     (uint32 tf32 bits) P tile 128x32
//   Vs    [64*36]      (uint32 tf32 bits) V^T tile 64x32
#define RPV_SMEM_FLOATS (128*129 + 128 + 128 + 256 + 128*36 + 64*36)

struct RowCtx {
    float l1v, inv_l1, ggv;
    int   irow;
};

__device__ __forceinline__ float fill16(
    uint32_t* Ps, int psbase, const float* s, float p0,
    const RowCtx& rc, int jbase)
{
    float run = 0.f, acc = 0.f;
    float fj = (float)(rc.irow - jbase);
    #pragma unroll
    for (int u = 0; u < 16; u++) {
        bool ok = (jbase + u) <= rc.irow;
        float e = ok ? __expf(s[u]) : 0.f;
        run += e;
        float suffix = rc.l1v - (p0 + run);
        float dsq    = suffix * rc.inv_l1 * (fj - (float)u);
        float dist   = sqrtf(fmaxf(dsq, 0.f));
        float eff    = fmaxf(__expf(dist * rc.ggv), 1e-5f);
        float e2     = ok ? __expf(eff * s[u]) : 0.f;
        acc += e2;
        Ps[psbase + u] = f2tf(e2);
    }
    return acc;
}

__global__ __launch_bounds__(256) void rowpv_kernel(const float* __restrict__ gammas)
{
    extern __shared__ float dynbuf[];
    float*    pre16 = dynbuf;                  // 128*129
    float*    l1s   = pre16 + 128*129;         // 128
    float*    ggs   = l1s + 128;               // 128
    float*    sl2   = ggs + 128;               // 256
    uint32_t* Ps    = (uint32_t*)(sl2 + 256);  // 128*36
    uint32_t* Vs    = Ps + 128*36;             // 64*36

    int qt = blockIdx.x, bh = blockIdx.y;
    int h  = bh & (HH - 1);
    int tid  = threadIdx.x;
    int wid  = tid >> 5, lane = tid & 31;

    const float* Sb = g_sc + (size_t)bh * SS * SS;
    int kmax  = (qt + 1) * 128;
    int nch16 = (qt + 1) * 8;

    // ---- per-row gamma prep ----
    if (tid < 128) {
        int i = qt*128 + tid;
        float gam = gammas[h * SS + i];
        float sp  = (gam > 20.f) ? gam : log1pf(__expf(gam));
        ggs[tid]  = -sp;
    }

    // ---- pass 1: per-row exp prefix table (warp w owns rows w*16..w*16+15) ----
    for (int rr = 0; rr < 16; rr++) {
        int row = wid * 16 + rr;
        int i   = qt*128 + row;
        const float* sr = Sb + (size_t)i * SS;
        float carry = 0.f;
        for (int base = 0; base < nch16; base += 32) {
            int c16 = base + lane;
            float sum = 0.f;
            if (c16 < nch16) {
                int col0 = c16 * 16;
                #pragma unroll
                for (int u4 = 0; u4 < 4; u4++) {
                    float4 v = *(const float4*)(sr + col0 + u4*4);
                    int j0 = col0 + u4*4;
                    sum += (j0+0 <= i) ? __expf(v.x) : 0.f;
                    sum += (j0+1 <= i) ? __expf(v.y) : 0.f;
                    sum += (j0+2 <= i) ? __expf(v.z) : 0.f;
                    sum += (j0+3 <= i) ? __expf(v.w) : 0.f;
                }
            }
            float x = sum;
            #pragma unroll
            for (int d = 1; d < 32; d <<= 1) {
                float y = __shfl_up_sync(0xffffffffu, x, d);
                if (lane >= d) x += y;
            }
            if (c16 < nch16) pre16[row*129 + c16] = carry + (x - sum);
            carry += __shfl_sync(0xffffffffu, x, 31);
        }
        if (lane == 0) l1s[row] = carry;
    }
    __syncthreads();

    // ---- pass 2: PV GEMM with on-the-fly P reconstruction ----
    int g    = lane >> 2, t = lane & 3;
    int wm   = wid >> 1, wn = wid & 1;
    int m0   = qt * 128;

    int lr   = tid >> 1;
    int lc   = (tid & 1) * 16;
    const float* sr2 = Sb + (size_t)(m0 + lr) * SS;

    RowCtx rc;
    rc.irow   = m0 + lr;
    rc.l1v    = l1s[lr];
    rc.inv_l1 = 1.f / rc.l1v;
    rc.ggv    = ggs[lr];
    const float* p16row = pre16 + lr*129;
    int psbase = lr*36 + lc;

    const uint32_t* vb = (const uint32_t*)g_vt + (size_t)bh * DKK * SS;
    int vrow0 = tid >> 3, vc0 = (tid & 7) * 4;
    int vrow1 = vrow0 + 32;

    float c[2][4][4];
    #pragma unroll
    for (int mf = 0; mf < 2; mf++)
        #pragma unroll
        for (int nf = 0; nf < 4; nf++)
            #pragma unroll
            for (int u = 0; u < 4; u++) c[mf][nf][u] = 0.f;

    float l2acc = 0.f;

    float sreg[16];
    uint4 vv[2];
    #pragma unroll
    for (int u4 = 0; u4 < 4; u4++) {
        float4 v = *(const float4*)(sr2 + lc + u4*4);
        sreg[u4*4+0]=v.x; sreg[u4*4+1]=v.y; sreg[u4*4+2]=v.z; sreg[u4*4+3]=v.w;
    }
    vv[0] = *(const uint4*)(vb + (size_t)vrow0 * SS + vc0);
    vv[1] = *(const uint4*)(vb + (size_t)vrow1 * SS + vc0);

    l2acc += fill16(Ps, psbase, sreg, p16row[(lc)>>4], rc, lc);
    *(uint4*)&Vs[vrow0*36 + vc0] = vv[0];
    *(uint4*)&Vs[vrow1*36 + vc0] = vv[1];
    __syncthreads();

    for (int k0 = 0; k0 < kmax; k0 += 32) {
        int kn = k0 + 32;
        if (kn < kmax) {
            #pragma unroll
            for (int u4 = 0; u4 < 4; u4++) {
                float4 v = *(const float4*)(sr2 + kn + lc + u4*4);
                sreg[u4*4+0]=v.x; sreg[u4*4+1]=v.y; sreg[u4*4+2]=v.z; sreg[u4*4+3]=v.w;
            }
            vv[0] = *(const uint4*)(vb + (size_t)vrow0 * SS + kn + vc0);
            vv[1] = *(const uint4*)(vb + (size_t)vrow1 * SS + kn + vc0);
        }
        #pragma unroll
        for (int k8 = 0; k8 < 32; k8 += 8) {
            uint32_t a[2][4], b[4][2];
            #pragma unroll
            for (int mf = 0; mf < 2; mf++) {
                int r = wm*32 + mf*16 + g;
                a[mf][0] = Ps[r*36 + k8+t];       a[mf][1] = Ps[(r+8)*36 + k8+t];
                a[mf][2] = Ps[r*36 + k8+t+4];     a[mf][3] = Ps[(r+8)*36 + k8+t+4];
            }
            #pragma unroll
            for (int nf = 0; nf < 4; nf++) {
                int rn = wn*32 + nf*8 + g;
                b[nf][0] = Vs[rn*36 + k8+t];      b[nf][1] = Vs[rn*36 + k8+t+4];
            }
            #pragma unroll
            for (int mf = 0; mf < 2; mf++)
                #pragma unroll
                for (int nf = 0; nf < 4; nf++)
                    mma8(c[mf][nf], a[mf], b[nf]);
        }
        __syncthreads();
        if (kn < kmax) {
            l2acc += fill16(Ps, psbase, sreg, p16row[(kn+lc)>>4], rc, kn + lc);
            *(uint4*)&Vs[vrow0*36 + vc0] = vv[0];
            *(uint4*)&Vs[vrow1*36 + vc0] = vv[1];
            __syncthreads();
        }
    }

    // ---- l2 reduce + scaled epilogue ----
    sl2[lr*2 + (tid & 1)] = l2acc;
    __syncthreads();

    int b = bh >> 3, hh = bh & 7;
    #pragma unroll
    for (int mf = 0; mf < 2; mf++) {
        #pragma unroll
        for (int half = 0; half < 2; half++) {
            int sl = wm*32 + mf*16 + g + half*8;
            int s  = m0 + sl;
            float l2v = sl2[sl*2] + sl2[sl*2 + 1];
            float sc  = (s == 0) ? 0.f : 1.f / l2v;
            #pragma unroll
            for (int nf = 0; nf < 4; nf++) {
                int dk = wn*32 + nf*8 + t*2;
                *(float2*)(g_at + ((size_t)b * SS + s) * DD + hh*64 + dk)
                    = make_float2(c[mf][nf][half*2+0] * sc,
                                  c[mf][nf][half*2+1] * sc);
            }
        }
    }
}

// ---------------- launcher ----------------------------------------------------
extern "C" void kernel_launch(void* const* d_in, const int* in_sizes, int n_in,
                              void* d_out, int out_size)
{
    const float* q      = (const float*)d_in[0];
    const float* k      = (const float*)d_in[1];
    const float* v      = (const float*)d_in[2];
    const float* Wq     = (const float*)d_in[5];
    const float* bq     = (const float*)d_in[6];
    const float* Wk     = (const float*)d_in[7];
    const float* bk     = (const float*)d_in[8];
    const float* Wv     = (const float*)d_in[9];
    const float* bv     = (const float*)d_in[10];
    const float* Wo     = (const float*)d_in[11];
    const float* bo     = (const float*)d_in[12];
    const float* gammas = (const float*)d_in[13];
    float* out = (float*)d_out;

    const int rpv_smem = RPV_SMEM_FLOATS * 4;
    cudaFuncSetAttribute(rowpv_kernel,
                         cudaFuncAttributeMaxDynamicSharedMemorySize, rpv_smem);

    rope_tab_kernel<<<(SS * 32 + 255) / 256, 256>>>();
    proj_kernel<<<dim3(4, 32, 3), 256>>>(q, k, v, Wq, bq, Wk, bk, Wv, bv);
    score_kernel<<<dim3(16, 16, 16), 256>>>();
    rowpv_kernel<<<dim3(16, 16), 256, rpv_smem>>>(gammas);
    out_proj_kernel<<<dim3(4, 32), 256>>>(Wo, bo, out);
}

// round 5
// speedup vs baseline: 1.2590x; 1.2590x over previous
#include <cuda_runtime.h>
#include <math.h>
#include <stdint.h>

#define BB   2
#define SS   2048
#define DD   512
#define HH   8
#define DKK  64
#define BHH  (BB*HH)

// ---------------- scratch (device globals; no allocation allowed) ----------
__device__ float g_qh[BHH*SS*DKK];          // [bh][s][dk] tf32 bits, pre-scaled 1/8
__device__ float g_kh[BHH*SS*DKK];          // tf32 bits
__device__ float g_vt[BHH*DKK*SS];          // V^T [bh][dk][s], tf32 bits
__device__ float g_at[BB*SS*DD];            // attention out [b][s][h*64+dk]
__device__ float g_cos[SS*DKK];
__device__ float g_sin[SS*DKK];
__device__ float g_sc[67108864];            // scores -> unnormalized P (tf32 bits)

// ---------------- helpers ----------------------------------------------------
__device__ __forceinline__ uint32_t f2tf(float f)
{
    uint32_t u;
    asm("cvt.rna.tf32.f32 %0, %1;" : "=r"(u) : "f"(f));
    return u;
}

__device__ __forceinline__ void mma8(float* c, const uint32_t* a, const uint32_t* b)
{
    asm volatile(
        "mma.sync.aligned.m16n8k8.row.col.f32.tf32.tf32.f32 "
        "{%0,%1,%2,%3}, {%4,%5,%6,%7}, {%8,%9}, {%0,%1,%2,%3};\n"
        : "+f"(c[0]), "+f"(c[1]), "+f"(c[2]), "+f"(c[3])
        : "r"(a[0]), "r"(a[1]), "r"(a[2]), "r"(a[3]), "r"(b[0]), "r"(b[1]));
}

// ---------------- RoPE table ------------------------------------------------
__global__ void rope_tab_kernel()
{
    int idx = blockIdx.x * blockDim.x + threadIdx.x;
    if (idx >= SS * 32) return;
    int s = idx >> 5;
    int m = idx & 31;
    float f = (float)s * powf(10000.f, -(float)(2 * m) / 64.f);
    float sn, cs;
    sincosf(f, &sn, &cs);
    g_cos[s*64 + 2*m]     = cs;
    g_cos[s*64 + 2*m + 1] = cs;
    g_sin[s*64 + 2*m]     = sn;
    g_sin[s*64 + 2*m + 1] = sn;
}

// ---------------- fused QKV projection + RoPE (tf32 mma, reg-prefetch) -------
__global__ __launch_bounds__(256) void proj_kernel(
    const float* __restrict__ qx, const float* __restrict__ kx, const float* __restrict__ vx,
    const float* __restrict__ Wq, const float* __restrict__ bq,
    const float* __restrict__ Wk, const float* __restrict__ bk,
    const float* __restrict__ Wv, const float* __restrict__ bv)
{
    __shared__ uint32_t As[128][36];
    __shared__ uint32_t Bs[128][36];

    int which = blockIdx.z;
    const float* X    = (which == 0) ? qx : (which == 1) ? kx : vx;
    const float* W    = (which == 0) ? Wq : (which == 1) ? Wk : Wv;
    const float* bias = (which == 0) ? bq : (which == 1) ? bk : bv;

    int tid  = threadIdx.x;
    int wid  = tid >> 5, lane = tid & 31;
    int g    = lane >> 2, t = lane & 3;
    int wm   = wid >> 2, wn = wid & 3;
    int n0   = blockIdx.x * 128;
    int m0   = blockIdx.y * 128;

    float c[4][4][4];
    #pragma unroll
    for (int mf = 0; mf < 4; mf++)
        #pragma unroll
        for (int nf = 0; nf < 4; nf++)
            #pragma unroll
            for (int u = 0; u < 4; u++) c[mf][nf][u] = 0.f;

    int lr = tid >> 1;
    int lc = (tid & 1) * 16;

    float4 xa[4], wb[4];
    #pragma unroll
    for (int u = 0; u < 4; u++) {
        xa[u] = *(const float4*)(X + (size_t)(m0 + lr) * 512 + lc + u*4);
        wb[u] = *(const float4*)(W + (size_t)(n0 + lr) * 512 + lc + u*4);
    }
    #pragma unroll
    for (int u = 0; u < 4; u++) {
        As[lr][lc+u*4+0] = f2tf(xa[u].x); As[lr][lc+u*4+1] = f2tf(xa[u].y);
        As[lr][lc+u*4+2] = f2tf(xa[u].z); As[lr][lc+u*4+3] = f2tf(xa[u].w);
        Bs[lr][lc+u*4+0] = f2tf(wb[u].x); Bs[lr][lc+u*4+1] = f2tf(wb[u].y);
        Bs[lr][lc+u*4+2] = f2tf(wb[u].z); Bs[lr][lc+u*4+3] = f2tf(wb[u].w);
    }
    __syncthreads();

    for (int k0 = 0; k0 < 512; k0 += 32) {
        int kn = k0 + 32;
        if (kn < 512) {
            #pragma unroll
            for (int u = 0; u < 4; u++) {
                xa[u] = *(const float4*)(X + (size_t)(m0 + lr) * 512 + kn + lc + u*4);
                wb[u] = *(const float4*)(W + (size_t)(n0 + lr) * 512 + kn + lc + u*4);
            }
        }
        #pragma unroll
        for (int k8 = 0; k8 < 32; k8 += 8) {
            uint32_t a[4][4], b[4][2];
            #pragma unroll
            for (int mf = 0; mf < 4; mf++) {
                int r = wm*64 + mf*16 + g;
                a[mf][0] = As[r][k8+t];     a[mf][1] = As[r+8][k8+t];
                a[mf][2] = As[r][k8+t+4];   a[mf][3] = As[r+8][k8+t+4];
            }
            #pragma unroll
            for (int nf = 0; nf < 4; nf++) {
                int rn = wn*32 + nf*8 + g;
                b[nf][0] = Bs[rn][k8+t];    b[nf][1] = Bs[rn][k8+t+4];
            }
            #pragma unroll
            for (int mf = 0; mf < 4; mf++)
                #pragma unroll
                for (int nf = 0; nf < 4; nf++)
                    mma8(c[mf][nf], a[mf], b[nf]);
        }
        __syncthreads();
        if (kn < 512) {
            #pragma unroll
            for (int u = 0; u < 4; u++) {
                As[lr][lc+u*4+0] = f2tf(xa[u].x); As[lr][lc+u*4+1] = f2tf(xa[u].y);
                As[lr][lc+u*4+2] = f2tf(xa[u].z); As[lr][lc+u*4+3] = f2tf(xa[u].w);
                Bs[lr][lc+u*4+0] = f2tf(wb[u].x); Bs[lr][lc+u*4+1] = f2tf(wb[u].y);
                Bs[lr][lc+u*4+2] = f2tf(wb[u].z); Bs[lr][lc+u*4+3] = f2tf(wb[u].w);
            }
            __syncthreads();
        }
    }

    // ---- epilogue: bias (+ RoPE for q/k); store tf32-rounded bits ----
    // q additionally pre-scaled by 1/8 (exact) so score kernel skips /8.
    #pragma unroll
    for (int nf = 0; nf < 4; nf++) {
        int col = n0 + wn*32 + nf*8 + t*2;
        int hh  = col >> 6, dk = col & 63;
        float bce = bias[col], bco = bias[col+1];
        #pragma unroll
        for (int mf = 0; mf < 4; mf++) {
            #pragma unroll
            for (int half = 0; half < 2; half++) {
                int row  = m0 + wm*64 + mf*16 + g + half*8;
                int srow = row & (SS-1);
                int bidx = row >> 11;
                float e = c[mf][nf][half*2+0] + bce;
                float o = c[mf][nf][half*2+1] + bco;
                if (which < 2) {
                    float cs = g_cos[srow*64 + dk];
                    float sn = g_sin[srow*64 + dk];
                    float sc = (which == 0) ? 0.125f : 1.0f;
                    float ne = __uint_as_float(f2tf((e*cs - o*sn) * sc));
                    float no = __uint_as_float(f2tf((o*cs + e*sn) * sc));
                    float* Y = (which == 0) ? g_qh : g_kh;
                    *(float2*)(Y + (((size_t)(bidx*HH + hh))*SS + srow)*DKK + dk)
                        = make_float2(ne, no);
                } else {
                    size_t vb = (size_t)(bidx*HH + hh) * DKK;
                    g_vt[(vb + dk    )*SS + srow] = __uint_as_float(f2tf(e));
                    g_vt[(vb + dk + 1)*SS + srow] = __uint_as_float(f2tf(o));
                }
            }
        }
    }
}

// ---------------- output projection (tf32 mma, reg-prefetch) -----------------
__global__ __launch_bounds__(256) void out_proj_kernel(
    const float* __restrict__ W, const float* __restrict__ bias, float* __restrict__ out)
{
    __shared__ uint32_t As[128][36];
    __shared__ uint32_t Bs[128][36];

    int tid  = threadIdx.x;
    int wid  = tid >> 5, lane = tid & 31;
    int g    = lane >> 2, t = lane & 3;
    int wm   = wid >> 2, wn = wid & 3;
    int n0   = blockIdx.x * 128;
    int m0   = blockIdx.y * 128;

    float c[4][4][4];
    #pragma unroll
    for (int mf = 0; mf < 4; mf++)
        #pragma unroll
        for (int nf = 0; nf < 4; nf++)
            #pragma unroll
            for (int u = 0; u < 4; u++) c[mf][nf][u] = 0.f;

    int lr = tid >> 1;
    int lc = (tid & 1) * 16;

    float4 xa[4], wb[4];
    #pragma unroll
    for (int u = 0; u < 4; u++) {
        xa[u] = *(const float4*)(g_at + (size_t)(m0 + lr) * 512 + lc + u*4);
        wb[u] = *(const float4*)(W    + (size_t)(n0 + lr) * 512 + lc + u*4);
    }
    #pragma unroll
    for (int u = 0; u < 4; u++) {
        As[lr][lc+u*4+0] = f2tf(xa[u].x); As[lr][lc+u*4+1] = f2tf(xa[u].y);
        As[lr][lc+u*4+2] = f2tf(xa[u].z); As[lr][lc+u*4+3] = f2tf(xa[u].w);
        Bs[lr][lc+u*4+0] = f2tf(wb[u].x); Bs[lr][lc+u*4+1] = f2tf(wb[u].y);
        Bs[lr][lc+u*4+2] = f2tf(wb[u].z); Bs[lr][lc+u*4+3] = f2tf(wb[u].w);
    }
    __syncthreads();

    for (int k0 = 0; k0 < 512; k0 += 32) {
        int kn = k0 + 32;
        if (kn < 512) {
            #pragma unroll
            for (int u = 0; u < 4; u++) {
                xa[u] = *(const float4*)(g_at + (size_t)(m0 + lr) * 512 + kn + lc + u*4);
                wb[u] = *(const float4*)(W    + (size_t)(n0 + lr) * 512 + kn + lc + u*4);
            }
        }
        #pragma unroll
        for (int k8 = 0; k8 < 32; k8 += 8) {
            uint32_t a[4][4], b[4][2];
            #pragma unroll
            for (int mf = 0; mf < 4; mf++) {
                int r = wm*64 + mf*16 + g;
                a[mf][0] = As[r][k8+t];     a[mf][1] = As[r+8][k8+t];
                a[mf][2] = As[r][k8+t+4];   a[mf][3] = As[r+8][k8+t+4];
            }
            #pragma unroll
            for (int nf = 0; nf < 4; nf++) {
                int rn = wn*32 + nf*8 + g;
                b[nf][0] = Bs[rn][k8+t];    b[nf][1] = Bs[rn][k8+t+4];
            }
            #pragma unroll
            for (int mf = 0; mf < 4; mf++)
                #pragma unroll
                for (int nf = 0; nf < 4; nf++)
                    mma8(c[mf][nf], a[mf], b[nf]);
        }
        __syncthreads();
        if (kn < 512) {
            #pragma unroll
            for (int u = 0; u < 4; u++) {
                As[lr][lc+u*4+0] = f2tf(xa[u].x); As[lr][lc+u*4+1] = f2tf(xa[u].y);
                As[lr][lc+u*4+2] = f2tf(xa[u].z); As[lr][lc+u*4+3] = f2tf(xa[u].w);
                Bs[lr][lc+u*4+0] = f2tf(wb[u].x); Bs[lr][lc+u*4+1] = f2tf(wb[u].y);
                Bs[lr][lc+u*4+2] = f2tf(wb[u].z); Bs[lr][lc+u*4+3] = f2tf(wb[u].w);
            }
            __syncthreads();
        }
    }

    #pragma unroll
    for (int nf = 0; nf < 4; nf++) {
        int col = n0 + wn*32 + nf*8 + t*2;
        float bce = bias[col], bco = bias[col+1];
        #pragma unroll
        for (int mf = 0; mf < 4; mf++) {
            #pragma unroll
            for (int half = 0; half < 2; half++) {
                int row = m0 + wm*64 + mf*16 + g + half*8;
                *(float2*)(out + (size_t)row*512 + col)
                    = make_float2(c[mf][nf][half*2+0] + bce, c[mf][nf][half*2+1] + bco);
            }
        }
    }
}

// ---------------- causal score GEMM S = Q K^T (q pre-scaled by 1/8) ----------
__global__ __launch_bounds__(256) void score_kernel()
{
    int qt = blockIdx.x, kt = blockIdx.y, bh = blockIdx.z;
    if (kt > qt) return;

    __shared__ uint32_t Qs[128][36];
    __shared__ uint32_t Ks[128][36];

    const uint32_t* qb = (const uint32_t*)g_qh + (size_t)bh * SS * DKK;
    const uint32_t* kb = (const uint32_t*)g_kh + (size_t)bh * SS * DKK;

    int tid  = threadIdx.x;
    int wid  = tid >> 5, lane = tid & 31;
    int g    = lane >> 2, t = lane & 3;
    int wm   = wid >> 2, wn = wid & 3;
    int i0   = qt * 128, j0 = kt * 128;

    float c[4][4][4];
    #pragma unroll
    for (int mf = 0; mf < 4; mf++)
        #pragma unroll
        for (int nf = 0; nf < 4; nf++)
            #pragma unroll
            for (int u = 0; u < 4; u++) c[mf][nf][u] = 0.f;

    int lr = tid >> 1;
    int lc = (tid & 1) * 16;

    uint4 qv[4], kv[4];
    #pragma unroll
    for (int u = 0; u < 4; u++) {
        qv[u] = *(const uint4*)(qb + (size_t)(i0 + lr) * 64 + lc + u*4);
        kv[u] = *(const uint4*)(kb + (size_t)(j0 + lr) * 64 + lc + u*4);
    }
    #pragma unroll
    for (int u = 0; u < 4; u++) {
        *(uint4*)&Qs[lr][lc+u*4] = qv[u];
        *(uint4*)&Ks[lr][lc+u*4] = kv[u];
    }
    __syncthreads();

    #pragma unroll
    for (int k0 = 0; k0 < 64; k0 += 32) {
        int kn = k0 + 32;
        if (kn < 64) {
            #pragma unroll
            for (int u = 0; u < 4; u++) {
                qv[u] = *(const uint4*)(qb + (size_t)(i0 + lr) * 64 + kn + lc + u*4);
                kv[u] = *(const uint4*)(kb + (size_t)(j0 + lr) * 64 + kn + lc + u*4);
            }
        }
        #pragma unroll
        for (int k8 = 0; k8 < 32; k8 += 8) {
            uint32_t a[4][4], b[4][2];
            #pragma unroll
            for (int mf = 0; mf < 4; mf++) {
                int r = wm*64 + mf*16 + g;
                a[mf][0] = Qs[r][k8+t];     a[mf][1] = Qs[r+8][k8+t];
                a[mf][2] = Qs[r][k8+t+4];   a[mf][3] = Qs[r+8][k8+t+4];
            }
            #pragma unroll
            for (int nf = 0; nf < 4; nf++) {
                int rn = wn*32 + nf*8 + g;
                b[nf][0] = Ks[rn][k8+t];    b[nf][1] = Ks[rn][k8+t+4];
            }
            #pragma unroll
            for (int mf = 0; mf < 4; mf++)
                #pragma unroll
                for (int nf = 0; nf < 4; nf++)
                    mma8(c[mf][nf], a[mf], b[nf]);
        }
        __syncthreads();
        if (kn < 64) {
            #pragma unroll
            for (int u = 0; u < 4; u++) {
                *(uint4*)&Qs[lr][lc+u*4] = qv[u];
                *(uint4*)&Ks[lr][lc+u*4] = kv[u];
            }
            __syncthreads();
        }
    }

    float* C = g_sc + (size_t)bh * SS * SS;
    #pragma unroll
    for (int nf = 0; nf < 4; nf++) {
        int col = j0 + wn*32 + nf*8 + t*2;
        #pragma unroll
        for (int mf = 0; mf < 4; mf++) {
            #pragma unroll
            for (int half = 0; half < 2; half++) {
                int row = i0 + wm*64 + mf*16 + g + half*8;
                *(float2*)(C + (size_t)row*SS + col)
                    = make_float2(c[mf][nf][half*2+0], c[mf][nf][half*2+1]);
            }
        }
    }
}

// ---------------- per-row decay softmax (no-max, unnormalized output) --------
// Writes unnormalized e2 = exp(eff*s) as tf32 bits. pv_kernel normalizes.
// Only collective: one block-wide prefix scan (2 barriers).
__global__ __launch_bounds__(256) void row_kernel(const float* __restrict__ gammas)
{
    __shared__ float swp[17];
    int rid = blockIdx.x;
    int bh  = rid >> 11;
    int i   = rid & (SS - 1);
    int h   = bh & (HH - 1);
    int tid = threadIdx.x, wid = tid >> 5, lane = tid & 31;

    float* row = g_sc + (size_t)bh * SS * SS + (size_t)i * SS;
    int lim = ((i >> 7) + 1) << 7;

    if (i == 0) {
        if (tid < 32) ((float4*)row)[tid] = make_float4(0.f, 0.f, 0.f, 0.f);
        return;
    }

    const bool act = (wid << 8) < lim;
    const int base = tid * 8;

    float sv[8];
    float epre[8];
    float run = 0.f;
    if (act) {
        float4 v0 = *(const float4*)(row + base);
        float4 v1 = *(const float4*)(row + base + 4);
        float tmp[8] = {v0.x, v0.y, v0.z, v0.w, v1.x, v1.y, v1.z, v1.w};
        #pragma unroll
        for (int u = 0; u < 8; u++) {
            sv[u] = (base + u <= i) ? tmp[u] : -3.0e38f;
            run  += __expf(sv[u]);          // masked lanes contribute exactly 0
            epre[u] = run;
        }
    }

    // --- block inclusive scan of per-thread sums (the only collective) ---
    float x = run;
    #pragma unroll
    for (int d = 1; d < 32; d <<= 1) {
        float y = __shfl_up_sync(0xffffffffu, x, d);
        if (lane >= d) x += y;
    }
    if (lane == 31) swp[wid] = x;
    __syncthreads();
    if (tid == 0) {
        float s = 0.f;
        #pragma unroll
        for (int w = 0; w < 8; w++) { float tw = swp[w]; swp[8 + w] = s; s += tw; }
        swp[16] = s;
    }
    __syncthreads();

    if (act) {
        float off = swp[8 + wid] + (x - run);
        float l1  = swp[16];
        float gam = gammas[h * SS + i];
        float sp  = (gam > 20.f) ? gam : log1pf(__expf(gam));
        float gg  = -sp;
        float inv_l1 = 1.f / l1;
        float fi  = (float)i - (float)base;

        uint32_t e2[8];
        #pragma unroll
        for (int u = 0; u < 8; u++) {
            float suffix = l1 - (off + epre[u]);
            float dsq    = suffix * inv_l1 * (fi - (float)u);
            float dist   = sqrtf(fmaxf(dsq, 0.f));
            float eff    = fmaxf(__expf(dist * gg), 1e-5f);
            e2[u] = f2tf(__expf(eff * sv[u]));    // masked -> exp(-huge) = 0
        }
        if (base < lim) {
            *(uint4*)(row + base)     = make_uint4(e2[0], e2[1], e2[2], e2[3]);
            *(uint4*)(row + base + 4) = make_uint4(e2[4], e2[5], e2[6], e2[7]);
        }
    }
}

// ---------------- causal PV GEMM O = P @ V, normalize in epilogue -------------
__global__ __launch_bounds__(256) void pv_kernel()
{
    int qt = (int)gridDim.x - 1 - (int)blockIdx.x;   // longest-k tiles first
    int bh = blockIdx.y;

    __shared__ uint32_t Ps[128][36];
    __shared__ uint32_t Vs[64][36];
    __shared__ float    sl2[256];

    const uint32_t* P  = (const uint32_t*)g_sc + (size_t)bh * SS * SS;
    const uint32_t* vb = (const uint32_t*)g_vt + (size_t)bh * DKK * SS;

    int tid  = threadIdx.x;
    int wid  = tid >> 5, lane = tid & 31;
    int g    = lane >> 2, t = lane & 3;
    int wm   = wid >> 1, wn = wid & 1;
    int m0   = qt * 128;

    float c[2][4][4];
    #pragma unroll
    for (int mf = 0; mf < 2; mf++)
        #pragma unroll
        for (int nf = 0; nf < 4; nf++)
            #pragma unroll
            for (int u = 0; u < 4; u++) c[mf][nf][u] = 0.f;

    int lr = tid >> 1;
    int lc = (tid & 1) * 16;
    int vrow0 = tid >> 3, vc0 = (tid & 7) * 4;
    int vrow1 = vrow0 + 32;
    int kmax = (qt + 1) * 128;

    float l2acc = 0.f;

    uint4 pv[4];
    uint4 vv[2];
    #pragma unroll
    for (int u = 0; u < 4; u++)
        pv[u] = *(const uint4*)(P + (size_t)(m0 + lr) * SS + lc + u*4);
    vv[0] = *(const uint4*)(vb + (size_t)vrow0 * SS + vc0);
    vv[1] = *(const uint4*)(vb + (size_t)vrow1 * SS + vc0);

    #pragma unroll
    for (int u = 0; u < 4; u++) {
        *(uint4*)&Ps[lr][lc+u*4] = pv[u];
        l2acc += __uint_as_float(pv[u].x) + __uint_as_float(pv[u].y)
               + __uint_as_float(pv[u].z) + __uint_as_float(pv[u].w);
    }
    *(uint4*)&Vs[vrow0][vc0] = vv[0];
    *(uint4*)&Vs[vrow1][vc0] = vv[1];
    __syncthreads();

    for (int k0 = 0; k0 < kmax; k0 += 32) {
        int kn = k0 + 32;
        if (kn < kmax) {
            #pragma unroll
            for (int u = 0; u < 4; u++)
                pv[u] = *(const uint4*)(P + (size_t)(m0 + lr) * SS + kn + lc + u*4);
            vv[0] = *(const uint4*)(vb + (size_t)vrow0 * SS + kn + vc0);
            vv[1] = *(const uint4*)(vb + (size_t)vrow1 * SS + kn + vc0);
        }
        #pragma unroll
        for (int k8 = 0; k8 < 32; k8 += 8) {
            uint32_t a[2][4], b[4][2];
            #pragma unroll
            for (int mf = 0; mf < 2; mf++) {
                int r = wm*32 + mf*16 + g;
                a[mf][0] = Ps[r][k8+t];     a[mf][1] = Ps[r+8][k8+t];
                a[mf][2] = Ps[r][k8+t+4];   a[mf][3] = Ps[r+8][k8+t+4];
            }
            #pragma unroll
            for (int nf = 0; nf < 4; nf++) {
                int rn = wn*32 + nf*8 + g;
                b[nf][0] = Vs[rn][k8+t];    b[nf][1] = Vs[rn][k8+t+4];
            }
            #pragma unroll
            for (int mf = 0; mf < 2; mf++)
                #pragma unroll
                for (int nf = 0; nf < 4; nf++)
                    mma8(c[mf][nf], a[mf], b[nf]);
        }
        __syncthreads();
        if (kn < kmax) {
            #pragma unroll
            for (int u = 0; u < 4; u++) {
                *(uint4*)&Ps[lr][lc+u*4] = pv[u];
                l2acc += __uint_as_float(pv[u].x) + __uint_as_float(pv[u].y)
                       + __uint_as_float(pv[u].z) + __uint_as_float(pv[u].w);
            }
            *(uint4*)&Vs[vrow0][vc0] = vv[0];
            *(uint4*)&Vs[vrow1][vc0] = vv[1];
            __syncthreads();
        }
    }

    // ---- per-row l2 reduce + normalized epilogue ----
    sl2[lr*2 + (tid & 1)] = l2acc;
    __syncthreads();

    int b = bh >> 3, h = bh & 7;
    #pragma unroll
    for (int mf = 0; mf < 2; mf++) {
        #pragma unroll
        for (int half = 0; half < 2; half++) {
            int sl = wm*32 + mf*16 + g + half*8;
            int s  = m0 + sl;
            float l2v = sl2[sl*2] + sl2[sl*2 + 1];
            float sc  = (s == 0) ? 0.f : 1.f / l2v;
            #pragma unroll
            for (int nf = 0; nf < 4; nf++) {
                int dk = wn*32 + nf*8 + t*2;
                *(float2*)(g_at + ((size_t)b * SS + s) * DD + h*64 + dk)
                    = make_float2(c[mf][nf][half*2+0] * sc,
                                  c[mf][nf][half*2+1] * sc);
            }
        }
    }
}

// ---------------- launcher ----------------------------------------------------
extern "C" void kernel_launch(void* const* d_in, const int* in_sizes, int n_in,
                              void* d_out, int out_size)
{
    const float* q      = (const float*)d_in[0];
    const float* k      = (const float*)d_in[1];
    const float* v      = (const float*)d_in[2];
    const float* Wq     = (const float*)d_in[5];
    const float* bq     = (const float*)d_in[6];
    const float* Wk     = (const float*)d_in[7];
    const float* bk     = (const float*)d_in[8];
    const float* Wv     = (const float*)d_in[9];
    const float* bv     = (const float*)d_in[10];
    const float* Wo     = (const float*)d_in[11];
    const float* bo     = (const float*)d_in[12];
    const float* gammas = (const float*)d_in[13];
    float* out = (float*)d_out;

    rope_tab_kernel<<<(SS * 32 + 255) / 256, 256>>>();
    proj_kernel<<<dim3(4, 32, 3), 256>>>(q, k, v, Wq, bq, Wk, bk, Wv, bv);
    score_kernel<<<dim3(16, 16, 16), 256>>>();
    row_kernel<<<BHH * SS, 256>>>(gammas);
    pv_kernel<<<dim3(16, 16), 256>>>();
    out_proj_kernel<<<dim3(4, 32), 256>>>(Wo, bo, out);
}

// round 6
// speedup vs baseline: 1.3070x; 1.0382x over previous
#include <cuda_runtime.h>
#include <math.h>
#include <stdint.h>

#define BB   2
#define SS   2048
#define DD   512
#define HH   8
#define DKK  64
#define BHH  (BB*HH)

// ---------------- scratch (device globals; no allocation allowed) ----------
__device__ float g_qh[BHH*SS*DKK];          // [bh][s][dk] tf32 bits, pre-scaled 1/8
__device__ float g_kh[BHH*SS*DKK];          // tf32 bits
__device__ float g_vt[BHH*DKK*SS];          // V^T [bh][dk][s], tf32 bits
__device__ float g_at[BB*SS*DD];            // attention out [b][s][h*64+dk]
__device__ float g_cos[SS*DKK];
__device__ float g_sin[SS*DKK];
__device__ float g_sc[67108864];            // scores -> unnormalized P (tf32 bits)

// ---------------- helpers ----------------------------------------------------
__device__ __forceinline__ uint32_t f2tf(float f)
{
    uint32_t u;
    asm("cvt.rna.tf32.f32 %0, %1;" : "=r"(u) : "f"(f));
    return u;
}

__device__ __forceinline__ void mma8(float* c, const uint32_t* a, const uint32_t* b)
{
    asm volatile(
        "mma.sync.aligned.m16n8k8.row.col.f32.tf32.tf32.f32 "
        "{%0,%1,%2,%3}, {%4,%5,%6,%7}, {%8,%9}, {%0,%1,%2,%3};\n"
        : "+f"(c[0]), "+f"(c[1]), "+f"(c[2]), "+f"(c[3])
        : "r"(a[0]), "r"(a[1]), "r"(a[2]), "r"(a[3]), "r"(b[0]), "r"(b[1]));
}

// ---------------- RoPE table ------------------------------------------------
__global__ void rope_tab_kernel()
{
    int idx = blockIdx.x * blockDim.x + threadIdx.x;
    if (idx >= SS * 32) return;
    int s = idx >> 5;
    int m = idx & 31;
    float f = (float)s * powf(10000.f, -(float)(2 * m) / 64.f);
    float sn, cs;
    sincosf(f, &sn, &cs);
    g_cos[s*64 + 2*m]     = cs;
    g_cos[s*64 + 2*m + 1] = cs;
    g_sin[s*64 + 2*m]     = sn;
    g_sin[s*64 + 2*m + 1] = sn;
}

// ---------------- fused QKV projection + RoPE (tf32 mma, reg-prefetch) -------
__global__ __launch_bounds__(256) void proj_kernel(
    const float* __restrict__ qx, const float* __restrict__ kx, const float* __restrict__ vx,
    const float* __restrict__ Wq, const float* __restrict__ bq,
    const float* __restrict__ Wk, const float* __restrict__ bk,
    const float* __restrict__ Wv, const float* __restrict__ bv)
{
    __shared__ uint32_t As[128][36];
    __shared__ uint32_t Bs[128][36];

    int which = blockIdx.z;
    const float* X    = (which == 0) ? qx : (which == 1) ? kx : vx;
    const float* W    = (which == 0) ? Wq : (which == 1) ? Wk : Wv;
    const float* bias = (which == 0) ? bq : (which == 1) ? bk : bv;

    int tid  = threadIdx.x;
    int wid  = tid >> 5, lane = tid & 31;
    int g    = lane >> 2, t = lane & 3;
    int wm   = wid >> 2, wn = wid & 3;
    int n0   = blockIdx.x * 128;
    int m0   = blockIdx.y * 128;

    float c[4][4][4];
    #pragma unroll
    for (int mf = 0; mf < 4; mf++)
        #pragma unroll
        for (int nf = 0; nf < 4; nf++)
            #pragma unroll
            for (int u = 0; u < 4; u++) c[mf][nf][u] = 0.f;

    int lr = tid >> 1;
    int lc = (tid & 1) * 16;

    float4 xa[4], wb[4];
    #pragma unroll
    for (int u = 0; u < 4; u++) {
        xa[u] = *(const float4*)(X + (size_t)(m0 + lr) * 512 + lc + u*4);
        wb[u] = *(const float4*)(W + (size_t)(n0 + lr) * 512 + lc + u*4);
    }
    #pragma unroll
    for (int u = 0; u < 4; u++) {
        As[lr][lc+u*4+0] = f2tf(xa[u].x); As[lr][lc+u*4+1] = f2tf(xa[u].y);
        As[lr][lc+u*4+2] = f2tf(xa[u].z); As[lr][lc+u*4+3] = f2tf(xa[u].w);
        Bs[lr][lc+u*4+0] = f2tf(wb[u].x); Bs[lr][lc+u*4+1] = f2tf(wb[u].y);
        Bs[lr][lc+u*4+2] = f2tf(wb[u].z); Bs[lr][lc+u*4+3] = f2tf(wb[u].w);
    }
    __syncthreads();

    for (int k0 = 0; k0 < 512; k0 += 32) {
        int kn = k0 + 32;
        if (kn < 512) {
            #pragma unroll
            for (int u = 0; u < 4; u++) {
                xa[u] = *(const float4*)(X + (size_t)(m0 + lr) * 512 + kn + lc + u*4);
                wb[u] = *(const float4*)(W + (size_t)(n0 + lr) * 512 + kn + lc + u*4);
            }
        }
        #pragma unroll
        for (int k8 = 0; k8 < 32; k8 += 8) {
            uint32_t a[4][4], b[4][2];
            #pragma unroll
            for (int mf = 0; mf < 4; mf++) {
                int r = wm*64 + mf*16 + g;
                a[mf][0] = As[r][k8+t];     a[mf][1] = As[r+8][k8+t];
                a[mf][2] = As[r][k8+t+4];   a[mf][3] = As[r+8][k8+t+4];
            }
            #pragma unroll
            for (int nf = 0; nf < 4; nf++) {
                int rn = wn*32 + nf*8 + g;
                b[nf][0] = Bs[rn][k8+t];    b[nf][1] = Bs[rn][k8+t+4];
            }
            #pragma unroll
            for (int mf = 0; mf < 4; mf++)
                #pragma unroll
                for (int nf = 0; nf < 4; nf++)
                    mma8(c[mf][nf], a[mf], b[nf]);
        }
        __syncthreads();
        if (kn < 512) {
            #pragma unroll
            for (int u = 0; u < 4; u++) {
                As[lr][lc+u*4+0] = f2tf(xa[u].x); As[lr][lc+u*4+1] = f2tf(xa[u].y);
                As[lr][lc+u*4+2] = f2tf(xa[u].z); As[lr][lc+u*4+3] = f2tf(xa[u].w);
                Bs[lr][lc+u*4+0] = f2tf(wb[u].x); Bs[lr][lc+u*4+1] = f2tf(wb[u].y);
                Bs[lr][lc+u*4+2] = f2tf(wb[u].z); Bs[lr][lc+u*4+3] = f2tf(wb[u].w);
            }
            __syncthreads();
        }
    }

    // ---- epilogue: bias (+ RoPE for q/k); store tf32-rounded bits ----
    // q additionally pre-scaled by 1/8 (exact) so score kernel skips /8.
    #pragma unroll
    for (int nf = 0; nf < 4; nf++) {
        int col = n0 + wn*32 + nf*8 + t*2;
        int hh  = col >> 6, dk = col & 63;
        float bce = bias[col], bco = bias[col+1];
        #pragma unroll
        for (int mf = 0; mf < 4; mf++) {
            #pragma unroll
            for (int half = 0; half < 2; half++) {
                int row  = m0 + wm*64 + mf*16 + g + half*8;
                int srow = row & (SS-1);
                int bidx = row >> 11;
                float e = c[mf][nf][half*2+0] + bce;
                float o = c[mf][nf][half*2+1] + bco;
                if (which < 2) {
                    float cs = g_cos[srow*64 + dk];
                    float sn = g_sin[srow*64 + dk];
                    float sc = (which == 0) ? 0.125f : 1.0f;
                    float ne = __uint_as_float(f2tf((e*cs - o*sn) * sc));
                    float no = __uint_as_float(f2tf((o*cs + e*sn) * sc));
                    float* Y = (which == 0) ? g_qh : g_kh;
                    *(float2*)(Y + (((size_t)(bidx*HH + hh))*SS + srow)*DKK + dk)
                        = make_float2(ne, no);
                } else {
                    size_t vb = (size_t)(bidx*HH + hh) * DKK;
                    g_vt[(vb + dk    )*SS + srow] = __uint_as_float(f2tf(e));
                    g_vt[(vb + dk + 1)*SS + srow] = __uint_as_float(f2tf(o));
                }
            }
        }
    }
}

// ---------------- output projection (tf32 mma, reg-prefetch) -----------------
__global__ __launch_bounds__(256) void out_proj_kernel(
    const float* __restrict__ W, const float* __restrict__ bias, float* __restrict__ out)
{
    __shared__ uint32_t As[128][36];
    __shared__ uint32_t Bs[128][36];

    int tid  = threadIdx.x;
    int wid  = tid >> 5, lane = tid & 31;
    int g    = lane >> 2, t = lane & 3;
    int wm   = wid >> 2, wn = wid & 3;
    int n0   = blockIdx.x * 128;
    int m0   = blockIdx.y * 128;

    float c[4][4][4];
    #pragma unroll
    for (int mf = 0; mf < 4; mf++)
        #pragma unroll
        for (int nf = 0; nf < 4; nf++)
            #pragma unroll
            for (int u = 0; u < 4; u++) c[mf][nf][u] = 0.f;

    int lr = tid >> 1;
    int lc = (tid & 1) * 16;

    float4 xa[4], wb[4];
    #pragma unroll
    for (int u = 0; u < 4; u++) {
        xa[u] = *(const float4*)(g_at + (size_t)(m0 + lr) * 512 + lc + u*4);
        wb[u] = *(const float4*)(W    + (size_t)(n0 + lr) * 512 + lc + u*4);
    }
    #pragma unroll
    for (int u = 0; u < 4; u++) {
        As[lr][lc+u*4+0] = f2tf(xa[u].x); As[lr][lc+u*4+1] = f2tf(xa[u].y);
        As[lr][lc+u*4+2] = f2tf(xa[u].z); As[lr][lc+u*4+3] = f2tf(xa[u].w);
        Bs[lr][lc+u*4+0] = f2tf(wb[u].x); Bs[lr][lc+u*4+1] = f2tf(wb[u].y);
        Bs[lr][lc+u*4+2] = f2tf(wb[u].z); Bs[lr][lc+u*4+3] = f2tf(wb[u].w);
    }
    __syncthreads();

    for (int k0 = 0; k0 < 512; k0 += 32) {
        int kn = k0 + 32;
        if (kn < 512) {
            #pragma unroll
            for (int u = 0; u < 4; u++) {
                xa[u] = *(const float4*)(g_at + (size_t)(m0 + lr) * 512 + kn + lc + u*4);
                wb[u] = *(const float4*)(W    + (size_t)(n0 + lr) * 512 + kn + lc + u*4);
            }
        }
        #pragma unroll
        for (int k8 = 0; k8 < 32; k8 += 8) {
            uint32_t a[4][4], b[4][2];
            #pragma unroll
            for (int mf = 0; mf < 4; mf++) {
                int r = wm*64 + mf*16 + g;
                a[mf][0] = As[r][k8+t];     a[mf][1] = As[r+8][k8+t];
                a[mf][2] = As[r][k8+t+4];   a[mf][3] = As[r+8][k8+t+4];
            }
            #pragma unroll
            for (int nf = 0; nf < 4; nf++) {
                int rn = wn*32 + nf*8 + g;
                b[nf][0] = Bs[rn][k8+t];    b[nf][1] = Bs[rn][k8+t+4];
            }
            #pragma unroll
            for (int mf = 0; mf < 4; mf++)
                #pragma unroll
                for (int nf = 0; nf < 4; nf++)
                    mma8(c[mf][nf], a[mf], b[nf]);
        }
        __syncthreads();
        if (kn < 512) {
            #pragma unroll
            for (int u = 0; u < 4; u++) {
                As[lr][lc+u*4+0] = f2tf(xa[u].x); As[lr][lc+u*4+1] = f2tf(xa[u].y);
                As[lr][lc+u*4+2] = f2tf(xa[u].z); As[lr][lc+u*4+3] = f2tf(xa[u].w);
                Bs[lr][lc+u*4+0] = f2tf(wb[u].x); Bs[lr][lc+u*4+1] = f2tf(wb[u].y);
                Bs[lr][lc+u*4+2] = f2tf(wb[u].z); Bs[lr][lc+u*4+3] = f2tf(wb[u].w);
            }
            __syncthreads();
        }
    }

    #pragma unroll
    for (int nf = 0; nf < 4; nf++) {
        int col = n0 + wn*32 + nf*8 + t*2;
        float bce = bias[col], bco = bias[col+1];
        #pragma unroll
        for (int mf = 0; mf < 4; mf++) {
            #pragma unroll
            for (int half = 0; half < 2; half++) {
                int row = m0 + wm*64 + mf*16 + g + half*8;
                *(float2*)(out + (size_t)row*512 + col)
                    = make_float2(c[mf][nf][half*2+0] + bce, c[mf][nf][half*2+1] + bco);
            }
        }
    }
}

// ---------------- causal score GEMM S = Q K^T (q pre-scaled by 1/8) ----------
__global__ __launch_bounds__(256) void score_kernel()
{
    int qt = blockIdx.x, kt = blockIdx.y, bh = blockIdx.z;
    if (kt > qt) return;

    __shared__ uint32_t Qs[128][36];
    __shared__ uint32_t Ks[128][36];

    const uint32_t* qb = (const uint32_t*)g_qh + (size_t)bh * SS * DKK;
    const uint32_t* kb = (const uint32_t*)g_kh + (size_t)bh * SS * DKK;

    int tid  = threadIdx.x;
    int wid  = tid >> 5, lane = tid & 31;
    int g    = lane >> 2, t = lane & 3;
    int wm   = wid >> 2, wn = wid & 3;
    int i0   = qt * 128, j0 = kt * 128;

    float c[4][4][4];
    #pragma unroll
    for (int mf = 0; mf < 4; mf++)
        #pragma unroll
        for (int nf = 0; nf < 4; nf++)
            #pragma unroll
            for (int u = 0; u < 4; u++) c[mf][nf][u] = 0.f;

    int lr = tid >> 1;
    int lc = (tid & 1) * 16;

    uint4 qv[4], kv[4];
    #pragma unroll
    for (int u = 0; u < 4; u++) {
        qv[u] = *(const uint4*)(qb + (size_t)(i0 + lr) * 64 + lc + u*4);
        kv[u] = *(const uint4*)(kb + (size_t)(j0 + lr) * 64 + lc + u*4);
    }
    #pragma unroll
    for (int u = 0; u < 4; u++) {
        *(uint4*)&Qs[lr][lc+u*4] = qv[u];
        *(uint4*)&Ks[lr][lc+u*4] = kv[u];
    }
    __syncthreads();

    #pragma unroll
    for (int k0 = 0; k0 < 64; k0 += 32) {
        int kn = k0 + 32;
        if (kn < 64) {
            #pragma unroll
            for (int u = 0; u < 4; u++) {
                qv[u] = *(const uint4*)(qb + (size_t)(i0 + lr) * 64 + kn + lc + u*4);
                kv[u] = *(const uint4*)(kb + (size_t)(j0 + lr) * 64 + kn + lc + u*4);
            }
        }
        #pragma unroll
        for (int k8 = 0; k8 < 32; k8 += 8) {
            uint32_t a[4][4], b[4][2];
            #pragma unroll
            for (int mf = 0; mf < 4; mf++) {
                int r = wm*64 + mf*16 + g;
                a[mf][0] = Qs[r][k8+t];     a[mf][1] = Qs[r+8][k8+t];
                a[mf][2] = Qs[r][k8+t+4];   a[mf][3] = Qs[r+8][k8+t+4];
            }
            #pragma unroll
            for (int nf = 0; nf < 4; nf++) {
                int rn = wn*32 + nf*8 + g;
                b[nf][0] = Ks[rn][k8+t];    b[nf][1] = Ks[rn][k8+t+4];
            }
            #pragma unroll
            for (int mf = 0; mf < 4; mf++)
                #pragma unroll
                for (int nf = 0; nf < 4; nf++)
                    mma8(c[mf][nf], a[mf], b[nf]);
        }
        __syncthreads();
        if (kn < 64) {
            #pragma unroll
            for (int u = 0; u < 4; u++) {
                *(uint4*)&Qs[lr][lc+u*4] = qv[u];
                *(uint4*)&Ks[lr][lc+u*4] = kv[u];
            }
            __syncthreads();
        }
    }

    float* C = g_sc + (size_t)bh * SS * SS;
    #pragma unroll
    for (int nf = 0; nf < 4; nf++) {
        int col = j0 + wn*32 + nf*8 + t*2;
        #pragma unroll
        for (int mf = 0; mf < 4; mf++) {
            #pragma unroll
            for (int half = 0; half < 2; half++) {
                int row = i0 + wm*64 + mf*16 + g + half*8;
                *(float2*)(C + (size_t)row*SS + col)
                    = make_float2(c[mf][nf][half*2+0], c[mf][nf][half*2+1]);
            }
        }
    }
}

// ---------------- per-row decay softmax (no-max, unnormalized output) --------
__global__ __launch_bounds__(256) void row_kernel(const float* __restrict__ gammas)
{
    __shared__ float swp[17];
    int rid = blockIdx.x;
    int bh  = rid >> 11;
    int i   = rid & (SS - 1);
    int h   = bh & (HH - 1);
    int tid = threadIdx.x, wid = tid >> 5, lane = tid & 31;

    float* row = g_sc + (size_t)bh * SS * SS + (size_t)i * SS;
    int lim = ((i >> 7) + 1) << 7;

    if (i == 0) {
        if (tid < 32) ((float4*)row)[tid] = make_float4(0.f, 0.f, 0.f, 0.f);
        return;
    }

    const bool act = (wid << 8) < lim;
    const int base = tid * 8;

    float sv[8];
    float epre[8];
    float run = 0.f;
    if (act) {
        float4 v0 = *(const float4*)(row + base);
        float4 v1 = *(const float4*)(row + base + 4);
        float tmp[8] = {v0.x, v0.y, v0.z, v0.w, v1.x, v1.y, v1.z, v1.w};
        #pragma unroll
        for (int u = 0; u < 8; u++) {
            sv[u] = (base + u <= i) ? tmp[u] : -3.0e38f;
            run  += __expf(sv[u]);          // masked lanes contribute exactly 0
            epre[u] = run;
        }
    }

    // --- block inclusive scan of per-thread sums (the only collective) ---
    float x = run;
    #pragma unroll
    for (int d = 1; d < 32; d <<= 1) {
        float y = __shfl_up_sync(0xffffffffu, x, d);
        if (lane >= d) x += y;
    }
    if (lane == 31) swp[wid] = x;
    __syncthreads();
    if (tid == 0) {
        float s = 0.f;
        #pragma unroll
        for (int w = 0; w < 8; w++) { float tw = swp[w]; swp[8 + w] = s; s += tw; }
        swp[16] = s;
    }
    __syncthreads();

    if (act) {
        float off = swp[8 + wid] + (x - run);
        float l1  = swp[16];
        float gam = gammas[h * SS + i];
        float sp  = (gam > 20.f) ? gam : log1pf(__expf(gam));
        float gg  = -sp;
        float inv_l1 = 1.f / l1;
        float fi  = (float)i - (float)base;

        uint32_t e2[8];
        #pragma unroll
        for (int u = 0; u < 8; u++) {
            float suffix = l1 - (off + epre[u]);
            float dsq    = suffix * inv_l1 * (fi - (float)u);
            float dist   = sqrtf(fmaxf(dsq, 0.f));
            float eff    = fmaxf(__expf(dist * gg), 1e-5f);
            e2[u] = f2tf(__expf(eff * sv[u]));    // masked -> exp(-huge) = 0
        }
        if (base < lim) {
            *(uint4*)(row + base)     = make_uint4(e2[0], e2[1], e2[2], e2[3]);
            *(uint4*)(row + base + 4) = make_uint4(e2[4], e2[5], e2[6], e2[7]);
        }
    }
}

// ---------------- causal PV GEMM O = P @ V (64-row tiles, 512 CTAs) -----------
// Normalize by per-row l2 (= sum of unnormalized P) in epilogue.
__global__ __launch_bounds__(256) void pv_kernel()
{
    int mt = (int)gridDim.x - 1 - (int)blockIdx.x;   // longest-k tiles first
    int bh = blockIdx.y;
    int qt = mt >> 1;                                // 128-aligned k-extent tile
    int m0 = mt * 64;

    __shared__ uint32_t Ps[64][36];
    __shared__ uint32_t Vs[64][36];
    __shared__ float    sl2[256];

    const uint32_t* P  = (const uint32_t*)g_sc + (size_t)bh * SS * SS;
    const uint32_t* vb = (const uint32_t*)g_vt + (size_t)bh * DKK * SS;

    int tid  = threadIdx.x;
    int wid  = tid >> 5, lane = tid & 31;
    int g    = lane >> 2, t = lane & 3;
    int wm   = wid >> 1, wn = wid & 1;               // 4 m-warps x 2 n-warps

    float c[4][4];
    #pragma unroll
    for (int nf = 0; nf < 4; nf++)
        #pragma unroll
        for (int u = 0; u < 4; u++) c[nf][u] = 0.f;

    int lr = tid >> 2;               // 0..63 (P/V fill row)
    int lc = (tid & 3) * 8;          // 0,8,16,24
    int kmax = (qt + 1) * 128;

    float l2acc = 0.f;

    uint4 pv[2], vv[2];
    pv[0] = *(const uint4*)(P + (size_t)(m0 + lr) * SS + lc);
    pv[1] = *(const uint4*)(P + (size_t)(m0 + lr) * SS + lc + 4);
    vv[0] = *(const uint4*)(vb + (size_t)lr * SS + lc);
    vv[1] = *(const uint4*)(vb + (size_t)lr * SS + lc + 4);

    #pragma unroll
    for (int u = 0; u < 2; u++) {
        *(uint4*)&Ps[lr][lc + u*4] = pv[u];
        *(uint4*)&Vs[lr][lc + u*4] = vv[u];
        l2acc += __uint_as_float(pv[u].x) + __uint_as_float(pv[u].y)
               + __uint_as_float(pv[u].z) + __uint_as_float(pv[u].w);
    }
    __syncthreads();

    for (int k0 = 0; k0 < kmax; k0 += 32) {
        int kn = k0 + 32;
        if (kn < kmax) {
            pv[0] = *(const uint4*)(P + (size_t)(m0 + lr) * SS + kn + lc);
            pv[1] = *(const uint4*)(P + (size_t)(m0 + lr) * SS + kn + lc + 4);
            vv[0] = *(const uint4*)(vb + (size_t)lr * SS + kn + lc);
            vv[1] = *(const uint4*)(vb + (size_t)lr * SS + kn + lc + 4);
        }
        #pragma unroll
        for (int k8 = 0; k8 < 32; k8 += 8) {
            uint32_t a[4], b[4][2];
            int r = wm*16 + g;
            a[0] = Ps[r][k8+t];     a[1] = Ps[r+8][k8+t];
            a[2] = Ps[r][k8+t+4];   a[3] = Ps[r+8][k8+t+4];
            #pragma unroll
            for (int nf = 0; nf < 4; nf++) {
                int rn = wn*32 + nf*8 + g;
                b[nf][0] = Vs[rn][k8+t];    b[nf][1] = Vs[rn][k8+t+4];
            }
            #pragma unroll
            for (int nf = 0; nf < 4; nf++)
                mma8(c[nf], a, b[nf]);
        }
        __syncthreads();
        if (kn < kmax) {
            #pragma unroll
            for (int u = 0; u < 2; u++) {
                *(uint4*)&Ps[lr][lc + u*4] = pv[u];
                *(uint4*)&Vs[lr][lc + u*4] = vv[u];
                l2acc += __uint_as_float(pv[u].x) + __uint_as_float(pv[u].y)
                       + __uint_as_float(pv[u].z) + __uint_as_float(pv[u].w);
            }
            __syncthreads();
        }
    }

    // ---- per-row l2 reduce (4 partials per row) + normalized epilogue ----
    sl2[lr*4 + (tid & 3)] = l2acc;
    __syncthreads();

    int b = bh >> 3, h = bh & 7;
    #pragma unroll
    for (int half = 0; half < 2; half++) {
        int sl = wm*16 + g + half*8;
        int s  = m0 + sl;
        float l2v = sl2[sl*4] + sl2[sl*4+1] + sl2[sl*4+2] + sl2[sl*4+3];
        float sc  = (s == 0) ? 0.f : 1.f / l2v;
        #pragma unroll
        for (int nf = 0; nf < 4; nf++) {
            int dk = wn*32 + nf*8 + t*2;
            *(float2*)(g_at + ((size_t)b * SS + s) * DD + h*64 + dk)
                = make_float2(c[nf][half*2+0] * sc, c[nf][half*2+1] * sc);
        }
    }
}

// ---------------- launcher ----------------------------------------------------
extern "C" void kernel_launch(void* const* d_in, const int* in_sizes, int n_in,
                              void* d_out, int out_size)
{
    const float* q      = (const float*)d_in[0];
    const float* k      = (const float*)d_in[1];
    const float* v      = (const float*)d_in[2];
    const float* Wq     = (const float*)d_in[5];
    const float* bq     = (const float*)d_in[6];
    const float* Wk     = (const float*)d_in[7];
    const float* bk     = (const float*)d_in[8];
    const float* Wv     = (const float*)d_in[9];
    const float* bv     = (const float*)d_in[10];
    const float* Wo     = (const float*)d_in[11];
    const float* bo     = (const float*)d_in[12];
    const float* gammas = (const float*)d_in[13];
    float* out = (float*)d_out;

    rope_tab_kernel<<<(SS * 32 + 255) / 256, 256>>>();
    proj_kernel<<<dim3(4, 32, 3), 256>>>(q, k, v, Wq, bq, Wk, bk, Wv, bv);
    score_kernel<<<dim3(16, 16, 16), 256>>>();
    row_kernel<<<BHH * SS, 256>>>(gammas);
    pv_kernel<<<dim3(32, 16), 256>>>();
    out_proj_kernel<<<dim3(4, 32), 256>>>(Wo, bo, out);
}